// round 4
// baseline (speedup 1.0000x reference)
#include <cuda_runtime.h>
#include <cstdint>

// Problem constants (reference: N_NODES=100000, N_EDGES=2000000, DIM=64)
#define MAX_NODES 100000
#define DIM 64

// Scratch (device globals — no allocation allowed)
__device__ float g_agg[MAX_NODES * DIM];   // 25.6 MB
__device__ float g_h1 [MAX_NODES * DIM];   // 25.6 MB
__device__ float g_deg[MAX_NODES];         // 0.4 MB

// ---------------------------------------------------------------------------
// Zero agg (+ optionally deg)
// ---------------------------------------------------------------------------
__global__ void zero_kernel(int n_nodes, int also_deg) {
    int total4 = n_nodes * (DIM / 4);
    float4 z = make_float4(0.f, 0.f, 0.f, 0.f);
    for (int i = blockIdx.x * blockDim.x + threadIdx.x; i < total4;
         i += gridDim.x * blockDim.x) {
        reinterpret_cast<float4*>(g_agg)[i] = z;
    }
    if (also_deg) {
        for (int i = blockIdx.x * blockDim.x + threadIdx.x; i < n_nodes;
             i += gridDim.x * blockDim.x) {
            g_deg[i] = 0.f;
        }
    }
}

// ---------------------------------------------------------------------------
// Degree: one thread per edge
// ---------------------------------------------------------------------------
__global__ void deg_kernel(const int* __restrict__ dst, int E) {
    int e = blockIdx.x * blockDim.x + threadIdx.x;
    if (e < E) atomicAdd(&g_deg[dst[e]], 1.0f);
}

// ---------------------------------------------------------------------------
// Scatter-add: agg[dst] += h[src].  16 threads per edge, float4 per thread,
// vector reduction red.global.add.v4.f32 (sm_90+) -> 4x fewer L2 atomic ops.
// ---------------------------------------------------------------------------
__global__ void scatter_kernel(const float* __restrict__ h,
                               const int* __restrict__ src,
                               const int* __restrict__ dst,
                               float* __restrict__ agg, int E) {
    int t = blockIdx.x * blockDim.x + threadIdx.x;
    int e = t >> 4;            // 16 threads per edge
    if (e >= E) return;
    int c = (t & 15) << 2;     // float offset 0..60 step 4
    int s = __ldg(&src[e]);
    int d = __ldg(&dst[e]);
    float4 v = *reinterpret_cast<const float4*>(h + s * DIM + c);
    float* p = agg + d * DIM + c;
    asm volatile("red.global.add.v4.f32 [%0], {%1,%2,%3,%4};"
                 :: "l"(p), "f"(v.x), "f"(v.y), "f"(v.z), "f"(v.w)
                 : "memory");
}

// ---------------------------------------------------------------------------
// Linear: out[n,:] = act( concat(h[n,:], agg[n,:]*inv_deg[n]) @ W + b )
// W: [128, 64] row-major ([in, out]).  Persistent blocks: W loaded into SMEM
// once per block; blocks stride over node tiles.
// blockDim = (64, NPB)
// ---------------------------------------------------------------------------
#define NPB 8
__global__ void linear_kernel(const float* __restrict__ h,
                              const float* __restrict__ agg,
                              const float* __restrict__ W,
                              const float* __restrict__ b,
                              float* __restrict__ out,
                              int n, int relu) {
    __shared__ float sW[2 * DIM * DIM];       // 128*64 floats = 32 KB
    __shared__ float sb[DIM];
    __shared__ float srow[NPB][2 * DIM];

    int tx = threadIdx.x;                      // 0..63 (output dim)
    int ty = threadIdx.y;                      // 0..NPB-1 (node in tile)
    int tid = ty * DIM + tx;
    int nthreads = DIM * NPB;

    for (int i = tid; i < 2 * DIM * DIM; i += nthreads) sW[i] = W[i];
    if (tid < DIM) sb[tid] = b[tid];
    __syncthreads();

    int ntiles = (n + NPB - 1) / NPB;
    for (int tile = blockIdx.x; tile < ntiles; tile += gridDim.x) {
        int node = tile * NPB + ty;
        if (node < n) {
            float inv = 1.0f / fmaxf(g_deg[node], 1.0f);
            srow[ty][tx]       = h[node * DIM + tx];
            srow[ty][DIM + tx] = agg[node * DIM + tx] * inv;
        }
        __syncthreads();
        if (node < n) {
            float acc = sb[tx];
#pragma unroll
            for (int k = 0; k < 2 * DIM; k++)
                acc = fmaf(srow[ty][k], sW[k * DIM + tx], acc);
            if (relu) acc = fmaxf(acc, 0.f);
            out[node * DIM + tx] = acc;
        }
        __syncthreads();
    }
}

// ---------------------------------------------------------------------------
// Launch
// Inputs (metadata order): x[100000*64] f32, edge_index[2*2000000] i32,
//                          W0[128*64] f32, b0[64] f32, W1[128*64] f32, b1[64] f32
// Output: [100000*64] f32
// ---------------------------------------------------------------------------
extern "C" void kernel_launch(void* const* d_in, const int* in_sizes, int n_in,
                              void* d_out, int out_size) {
    const float* x  = (const float*)d_in[0];
    const int*   ei = (const int*)  d_in[1];
    const float* W0 = (const float*)d_in[2];
    const float* b0 = (const float*)d_in[3];
    const float* W1 = (const float*)d_in[4];
    const float* b1 = (const float*)d_in[5];
    float* out = (float*)d_out;

    int n = in_sizes[0] / DIM;          // 100000
    int E = in_sizes[1] / 2;            // 2000000
    const int* src = ei;
    const int* dst = ei + E;

    float* agg;  cudaGetSymbolAddress((void**)&agg, g_agg);
    float* h1;   cudaGetSymbolAddress((void**)&h1,  g_h1);

    // zero agg + deg
    zero_kernel<<<1184, 256>>>(n, 1);
    // degree
    deg_kernel<<<(E + 255) / 256, 256>>>(dst, E);

    // ---- layer 0 ----
    {
        long long threads = (long long)E * 16;
        int blocks = (int)((threads + 255) / 256);
        scatter_kernel<<<blocks, 256>>>(x, src, dst, agg, E);
    }
    {
        dim3 blk(DIM, NPB);
        linear_kernel<<<592, blk>>>(x, agg, W0, b0, h1, n, /*relu=*/1);
    }

    // ---- layer 1 ----
    zero_kernel<<<1184, 256>>>(n, 0);
    {
        long long threads = (long long)E * 16;
        int blocks = (int)((threads + 255) / 256);
        scatter_kernel<<<blocks, 256>>>(h1, src, dst, agg, E);
    }
    {
        dim3 blk(DIM, NPB);
        linear_kernel<<<592, blk>>>(h1, agg, W1, b1, out, n, /*relu=*/0);
    }
}

// round 5
// speedup vs baseline: 1.0026x; 1.0026x over previous
#include <cuda_runtime.h>
#include <cstdint>

// Problem constants (reference: N_NODES=100000, N_EDGES=2000000, DIM=64)
#define MAX_NODES 100000
#define DIM 64

// Scratch (device globals — no allocation allowed)
__device__ float g_agg[MAX_NODES * DIM];   // 25.6 MB
__device__ float g_h1 [MAX_NODES * DIM];   // 25.6 MB
__device__ float g_deg[MAX_NODES];         // 0.4 MB

// ---------------------------------------------------------------------------
// Zero agg (+ optionally deg)
// ---------------------------------------------------------------------------
__global__ void zero_kernel(int n_nodes, int also_deg) {
    int total4 = n_nodes * (DIM / 4);
    float4 z = make_float4(0.f, 0.f, 0.f, 0.f);
    for (int i = blockIdx.x * blockDim.x + threadIdx.x; i < total4;
         i += gridDim.x * blockDim.x) {
        reinterpret_cast<float4*>(g_agg)[i] = z;
    }
    if (also_deg) {
        for (int i = blockIdx.x * blockDim.x + threadIdx.x; i < n_nodes;
             i += gridDim.x * blockDim.x) {
            g_deg[i] = 0.f;
        }
    }
}

// ---------------------------------------------------------------------------
// Degree: one thread per edge
// ---------------------------------------------------------------------------
__global__ void deg_kernel(const int* __restrict__ dst, int E) {
    int e = blockIdx.x * blockDim.x + threadIdx.x;
    if (e < E) atomicAdd(&g_deg[dst[e]], 1.0f);
}

// ---------------------------------------------------------------------------
// Scatter-add: agg[dst] += h[src].  16 threads per edge, float4 per thread,
// vector reduction red.global.add.v4.f32 (sm_90+) -> 4x fewer L2 atomic ops.
// ---------------------------------------------------------------------------
__global__ void scatter_kernel(const float* __restrict__ h,
                               const int* __restrict__ src,
                               const int* __restrict__ dst,
                               float* __restrict__ agg, int E) {
    int t = blockIdx.x * blockDim.x + threadIdx.x;
    int e = t >> 4;            // 16 threads per edge
    if (e >= E) return;
    int c = (t & 15) << 2;     // float offset 0..60 step 4
    int s = __ldg(&src[e]);
    int d = __ldg(&dst[e]);
    float4 v = *reinterpret_cast<const float4*>(h + s * DIM + c);
    float* p = agg + d * DIM + c;
    asm volatile("red.global.add.v4.f32 [%0], {%1,%2,%3,%4};"
                 :: "l"(p), "f"(v.x), "f"(v.y), "f"(v.z), "f"(v.w)
                 : "memory");
}

// ---------------------------------------------------------------------------
// Linear: out[n,:] = act( concat(h[n,:], agg[n,:]*inv_deg[n]) @ W + b )
// W: [128, 64] row-major ([in, out]).  Persistent blocks: W loaded into SMEM
// once per block; blocks stride over node tiles.
// blockDim = (64, NPB)
// ---------------------------------------------------------------------------
#define NPB 8
__global__ void linear_kernel(const float* __restrict__ h,
                              const float* __restrict__ agg,
                              const float* __restrict__ W,
                              const float* __restrict__ b,
                              float* __restrict__ out,
                              int n, int relu) {
    __shared__ float sW[2 * DIM * DIM];       // 128*64 floats = 32 KB
    __shared__ float sb[DIM];
    __shared__ float srow[NPB][2 * DIM];

    int tx = threadIdx.x;                      // 0..63 (output dim)
    int ty = threadIdx.y;                      // 0..NPB-1 (node in tile)
    int tid = ty * DIM + tx;
    int nthreads = DIM * NPB;

    for (int i = tid; i < 2 * DIM * DIM; i += nthreads) sW[i] = W[i];
    if (tid < DIM) sb[tid] = b[tid];
    __syncthreads();

    int ntiles = (n + NPB - 1) / NPB;
    for (int tile = blockIdx.x; tile < ntiles; tile += gridDim.x) {
        int node = tile * NPB + ty;
        if (node < n) {
            float inv = 1.0f / fmaxf(g_deg[node], 1.0f);
            srow[ty][tx]       = h[node * DIM + tx];
            srow[ty][DIM + tx] = agg[node * DIM + tx] * inv;
        }
        __syncthreads();
        if (node < n) {
            float acc = sb[tx];
#pragma unroll
            for (int k = 0; k < 2 * DIM; k++)
                acc = fmaf(srow[ty][k], sW[k * DIM + tx], acc);
            if (relu) acc = fmaxf(acc, 0.f);
            out[node * DIM + tx] = acc;
        }
        __syncthreads();
    }
}

// ---------------------------------------------------------------------------
// Launch
// Inputs (metadata order): x[100000*64] f32, edge_index[2*2000000] i32,
//                          W0[128*64] f32, b0[64] f32, W1[128*64] f32, b1[64] f32
// Output: [100000*64] f32
// ---------------------------------------------------------------------------
extern "C" void kernel_launch(void* const* d_in, const int* in_sizes, int n_in,
                              void* d_out, int out_size) {
    const float* x  = (const float*)d_in[0];
    const int*   ei = (const int*)  d_in[1];
    const float* W0 = (const float*)d_in[2];
    const float* b0 = (const float*)d_in[3];
    const float* W1 = (const float*)d_in[4];
    const float* b1 = (const float*)d_in[5];
    float* out = (float*)d_out;

    int n = in_sizes[0] / DIM;          // 100000
    int E = in_sizes[1] / 2;            // 2000000
    const int* src = ei;
    const int* dst = ei + E;

    float* agg;  cudaGetSymbolAddress((void**)&agg, g_agg);
    float* h1;   cudaGetSymbolAddress((void**)&h1,  g_h1);

    // zero agg + deg
    zero_kernel<<<1184, 256>>>(n, 1);
    // degree
    deg_kernel<<<(E + 255) / 256, 256>>>(dst, E);

    // ---- layer 0 ----
    {
        long long threads = (long long)E * 16;
        int blocks = (int)((threads + 255) / 256);
        scatter_kernel<<<blocks, 256>>>(x, src, dst, agg, E);
    }
    {
        dim3 blk(DIM, NPB);
        linear_kernel<<<592, blk>>>(x, agg, W0, b0, h1, n, /*relu=*/1);
    }

    // ---- layer 1 ----
    zero_kernel<<<1184, 256>>>(n, 0);
    {
        long long threads = (long long)E * 16;
        int blocks = (int)((threads + 255) / 256);
        scatter_kernel<<<blocks, 256>>>(h1, src, dst, agg, E);
    }
    {
        dim3 blk(DIM, NPB);
        linear_kernel<<<592, blk>>>(h1, agg, W1, b1, out, n, /*relu=*/0);
    }
}

// round 6
// speedup vs baseline: 1.4872x; 1.4834x over previous
#include <cuda_runtime.h>
#include <cstdint>

// Problem constants (reference: N_NODES=100000, N_EDGES=2000000, DIM=64)
#define MAX_NODES 100000
#define DIM 64

// Scratch (device globals — no allocation allowed)
__device__ float g_agg[MAX_NODES * DIM];   // 25.6 MB
__device__ float g_h1 [MAX_NODES * DIM];   // 25.6 MB
__device__ float g_deg[MAX_NODES];         // 0.4 MB

// ---------------------------------------------------------------------------
// Zero agg (+ optionally deg)
// ---------------------------------------------------------------------------
__global__ void zero_kernel(int n_nodes, int also_deg) {
    int total4 = n_nodes * (DIM / 4);
    float4 z = make_float4(0.f, 0.f, 0.f, 0.f);
    for (int i = blockIdx.x * blockDim.x + threadIdx.x; i < total4;
         i += gridDim.x * blockDim.x) {
        reinterpret_cast<float4*>(g_agg)[i] = z;
    }
    if (also_deg) {
        for (int i = blockIdx.x * blockDim.x + threadIdx.x; i < n_nodes;
             i += gridDim.x * blockDim.x) {
            g_deg[i] = 0.f;
        }
    }
}

// ---------------------------------------------------------------------------
// Scatter-add: agg[dst] += h[src].  16 threads per edge, float4 per thread,
// vector reduction red.global.add.v4.f32 -> 4x fewer L2 atomic ops.
// Layer 0 additionally accumulates degree (lane with c==0).
// ---------------------------------------------------------------------------
__global__ void scatter_kernel(const float* __restrict__ h,
                               const int* __restrict__ src,
                               const int* __restrict__ dst,
                               float* __restrict__ agg, int E, int do_deg) {
    int t = blockIdx.x * blockDim.x + threadIdx.x;
    int e = t >> 4;            // 16 threads per edge
    if (e >= E) return;
    int c = (t & 15) << 2;     // float offset 0..60 step 4
    int s = __ldg(&src[e]);
    int d = __ldg(&dst[e]);
    if (do_deg && c == 0) atomicAdd(&g_deg[d], 1.0f);
    float4 v = *reinterpret_cast<const float4*>(h + s * DIM + c);
    float* p = agg + d * DIM + c;
    asm volatile("red.global.add.v4.f32 [%0], {%1,%2,%3,%4};"
                 :: "l"(p), "f"(v.x), "f"(v.y), "f"(v.z), "f"(v.w)
                 : "memory");
}

// ---------------------------------------------------------------------------
// Linear v2: out[n,:] = act( concat(h[n,:], agg[n,:]*inv_deg[n]) @ W + b )
// Register-tiled: block tile = 64 nodes x 64 cols, 256 threads,
// each thread computes 4 nodes x 4 cols (16 accumulators).
// Inner loop per k-quad: 8x LDS.128 feeding 64 FFMA (1:8 LDS:FMA ratio).
//
// Dynamic smem layout (floats):
//   sW   [128*64]       = 8192
//   sb   [64]           = 64
//   srow [64][132]      = 8448   (stride 132 avoids 8-way bank conflicts)
// total 16704 floats = 66816 bytes
// ---------------------------------------------------------------------------
#define SROW_STRIDE 132
#define SMEM_FLOATS (8192 + 64 + 64 * SROW_STRIDE)

__global__ __launch_bounds__(256) void linear_kernel(
        const float* __restrict__ h,
        const float* __restrict__ agg,
        const float* __restrict__ W,
        const float* __restrict__ b,
        float* __restrict__ out,
        int n, int relu) {
    extern __shared__ float smem[];
    float* sW   = smem;                 // [128][64]
    float* sb   = smem + 8192;          // [64]
    float* srow = smem + 8192 + 64;     // [64][SROW_STRIDE]

    int tid = threadIdx.x;

    // load W + b once per block
    for (int i = tid; i < 2 * DIM * DIM; i += 256) sW[i] = W[i];
    if (tid < DIM) sb[tid] = b[tid];
    __syncthreads();

    int cg = tid & 15;        // col group: cols cg*4 .. cg*4+3
    int ng = tid >> 4;        // node group: nodes ng*4 .. ng*4+3
    int c0 = cg << 2;

    int ntiles = (n + 63) >> 6;
    for (int tile = blockIdx.x; tile < ntiles; tile += gridDim.x) {
        int base = tile << 6;

        // ---- stage srow: [64 nodes][128] = concat(h, agg*inv_deg) ----
        // 2048 float4 total; 8 per thread
#pragma unroll
        for (int it = 0; it < 8; it++) {
            int idx = it * 256 + tid;       // 0..2047
            int row = idx >> 5;             // node within tile
            int q   = idx & 31;             // float4 index within 128-float row
            int node = base + row;
            if (node < n) {
                float4 v;
                if (q < 16) {
                    v = *reinterpret_cast<const float4*>(h + node * DIM + (q << 2));
                } else {
                    float inv = 1.0f / fmaxf(g_deg[node], 1.0f);
                    v = *reinterpret_cast<const float4*>(agg + node * DIM + ((q - 16) << 2));
                    v.x *= inv; v.y *= inv; v.z *= inv; v.w *= inv;
                }
                *reinterpret_cast<float4*>(&srow[row * SROW_STRIDE + (q << 2)]) = v;
            }
        }
        __syncthreads();

        // ---- compute 4 nodes x 4 cols ----
        float4 bv = *reinterpret_cast<const float4*>(&sb[c0]);
        float acc[4][4];
#pragma unroll
        for (int i = 0; i < 4; i++) {
            acc[i][0] = bv.x; acc[i][1] = bv.y; acc[i][2] = bv.z; acc[i][3] = bv.w;
        }

        int nb = ng << 2;  // first node row of this thread within tile
#pragma unroll 4
        for (int k = 0; k < 2 * DIM; k += 4) {
            float4 hv[4];
#pragma unroll
            for (int i = 0; i < 4; i++)
                hv[i] = *reinterpret_cast<const float4*>(&srow[(nb + i) * SROW_STRIDE + k]);
            float4 wv[4];
#pragma unroll
            for (int kk = 0; kk < 4; kk++)
                wv[kk] = *reinterpret_cast<const float4*>(&sW[(k + kk) * DIM + c0]);
#pragma unroll
            for (int i = 0; i < 4; i++) {
                acc[i][0] = fmaf(hv[i].x, wv[0].x, acc[i][0]);
                acc[i][1] = fmaf(hv[i].x, wv[0].y, acc[i][1]);
                acc[i][2] = fmaf(hv[i].x, wv[0].z, acc[i][2]);
                acc[i][3] = fmaf(hv[i].x, wv[0].w, acc[i][3]);
                acc[i][0] = fmaf(hv[i].y, wv[1].x, acc[i][0]);
                acc[i][1] = fmaf(hv[i].y, wv[1].y, acc[i][1]);
                acc[i][2] = fmaf(hv[i].y, wv[1].z, acc[i][2]);
                acc[i][3] = fmaf(hv[i].y, wv[1].w, acc[i][3]);
                acc[i][0] = fmaf(hv[i].z, wv[2].x, acc[i][0]);
                acc[i][1] = fmaf(hv[i].z, wv[2].y, acc[i][1]);
                acc[i][2] = fmaf(hv[i].z, wv[2].z, acc[i][2]);
                acc[i][3] = fmaf(hv[i].z, wv[2].w, acc[i][3]);
                acc[i][0] = fmaf(hv[i].w, wv[3].x, acc[i][0]);
                acc[i][1] = fmaf(hv[i].w, wv[3].y, acc[i][1]);
                acc[i][2] = fmaf(hv[i].w, wv[3].z, acc[i][2]);
                acc[i][3] = fmaf(hv[i].w, wv[3].w, acc[i][3]);
            }
        }

        // ---- epilogue ----
#pragma unroll
        for (int i = 0; i < 4; i++) {
            int node = base + nb + i;
            if (node < n) {
                float4 r = make_float4(acc[i][0], acc[i][1], acc[i][2], acc[i][3]);
                if (relu) {
                    r.x = fmaxf(r.x, 0.f); r.y = fmaxf(r.y, 0.f);
                    r.z = fmaxf(r.z, 0.f); r.w = fmaxf(r.w, 0.f);
                }
                *reinterpret_cast<float4*>(out + node * DIM + c0) = r;
            }
        }
        __syncthreads();   // protect srow before next tile's staging
    }
}

// ---------------------------------------------------------------------------
// Launch
// Inputs: x[100000*64] f32, edge_index[2*2000000] i32,
//         W0[128*64] f32, b0[64] f32, W1[128*64] f32, b1[64] f32
// Output: [100000*64] f32
// ---------------------------------------------------------------------------
extern "C" void kernel_launch(void* const* d_in, const int* in_sizes, int n_in,
                              void* d_out, int out_size) {
    const float* x  = (const float*)d_in[0];
    const int*   ei = (const int*)  d_in[1];
    const float* W0 = (const float*)d_in[2];
    const float* b0 = (const float*)d_in[3];
    const float* W1 = (const float*)d_in[4];
    const float* b1 = (const float*)d_in[5];
    float* out = (float*)d_out;

    int n = in_sizes[0] / DIM;          // 100000
    int E = in_sizes[1] / 2;            // 2000000
    const int* src = ei;
    const int* dst = ei + E;

    float* agg;  cudaGetSymbolAddress((void**)&agg, g_agg);
    float* h1;   cudaGetSymbolAddress((void**)&h1,  g_h1);

    static int smem_set = 0;
    size_t smem_bytes = SMEM_FLOATS * sizeof(float);
    if (!smem_set) {
        cudaFuncSetAttribute(linear_kernel,
                             cudaFuncAttributeMaxDynamicSharedMemorySize,
                             (int)smem_bytes);
        smem_set = 1;
    }

    int scat_blocks = (int)(((long long)E * 16 + 255) / 256);

    // zero agg + deg
    zero_kernel<<<1184, 256>>>(n, 1);

    // ---- layer 0 (scatter also accumulates degree) ----
    scatter_kernel<<<scat_blocks, 256>>>(x, src, dst, agg, E, /*do_deg=*/1);
    linear_kernel<<<444, 256, smem_bytes>>>(x, agg, W0, b0, h1, n, /*relu=*/1);

    // ---- layer 1 ----
    zero_kernel<<<1184, 256>>>(n, 0);
    scatter_kernel<<<scat_blocks, 256>>>(h1, src, dst, agg, E, /*do_deg=*/0);
    linear_kernel<<<444, 256, smem_bytes>>>(h1, agg, W1, b1, out, n, /*relu=*/0);
}

// round 8
// speedup vs baseline: 2.3644x; 1.5899x over previous
#include <cuda_runtime.h>
#include <cstdint>

// Problem constants (reference: N_NODES=100000, N_EDGES=2000000, DIM=64)
#define MAX_NODES 100000
#define MAX_EDGES 2000000
#define DIM 64

// Scratch (device globals — no allocation allowed)
__device__ float g_agg[MAX_NODES * DIM];     // 25.6 MB
__device__ float g_h1 [MAX_NODES * DIM];     // 25.6 MB
__device__ int   g_cnt [MAX_NODES];          // per-node degree (int)
__device__ int   g_scan[MAX_NODES];          // block-local exclusive scans
__device__ int   g_part[256];                // per-block partial sums
__device__ int   g_rowptr[MAX_NODES + 1];    // CSR row pointers
__device__ int   g_pos [MAX_NODES];          // fill cursors
__device__ int   g_csr [MAX_EDGES];          // CSR column (src) indices

// ---------------------------------------------------------------------------
// CSR build step 0: zero degree counters
// ---------------------------------------------------------------------------
__global__ void zero_cnt_kernel(int n) {
    int i = blockIdx.x * blockDim.x + threadIdx.x;
    if (i < n) g_cnt[i] = 0;
}

// CSR build step 1: count degrees
__global__ void deg_count_kernel(const int* __restrict__ dst, int E) {
    int e = blockIdx.x * blockDim.x + threadIdx.x;
    if (e < E) atomicAdd(&g_cnt[dst[e]], 1);
}

// CSR build step 2a: per-block exclusive scan (block=1024) + block totals
__global__ __launch_bounds__(1024) void scanA_kernel(int n) {
    int tid = threadIdx.x, lane = tid & 31, wid = tid >> 5;
    int i = blockIdx.x * 1024 + tid;
    int v = (i < n) ? g_cnt[i] : 0;
    int incl = v;
#pragma unroll
    for (int off = 1; off < 32; off <<= 1) {
        int t = __shfl_up_sync(0xffffffffu, incl, off);
        if (lane >= off) incl += t;
    }
    __shared__ int wsum[32];
    if (lane == 31) wsum[wid] = incl;
    __syncthreads();
    if (wid == 0) {
        int w = wsum[lane];
        int wi = w;
#pragma unroll
        for (int off = 1; off < 32; off <<= 1) {
            int t = __shfl_up_sync(0xffffffffu, wi, off);
            if (lane >= off) wi += t;
        }
        wsum[lane] = wi - w;   // exclusive warp offset
    }
    __syncthreads();
    int excl = incl - v + wsum[wid];
    if (i < n) g_scan[i] = excl;
    if (tid == 1023) g_part[blockIdx.x] = excl + v;   // block total
}

// CSR build step 2b: scan block partials (tiny, serial)
__global__ void scanB_kernel(int nb, int n, int E) {
    if (threadIdx.x == 0 && blockIdx.x == 0) {
        int acc = 0;
        for (int i = 0; i < nb; i++) { int t = g_part[i]; g_part[i] = acc; acc += t; }
        g_rowptr[n] = E;
    }
}

// CSR build step 2c: add block offsets -> row_ptr; zero fill cursors
__global__ __launch_bounds__(1024) void scanC_kernel(int n) {
    int i = blockIdx.x * 1024 + threadIdx.x;
    if (i < n) {
        g_rowptr[i] = g_scan[i] + g_part[blockIdx.x];
        g_pos[i] = 0;
    }
}

// CSR build step 3: scatter edges into CSR slots
__global__ void fill_kernel(const int* __restrict__ src,
                            const int* __restrict__ dst, int E) {
    int e = blockIdx.x * blockDim.x + threadIdx.x;
    if (e >= E) return;
    int d = dst[e];
    int p = atomicAdd(&g_pos[d], 1);
    g_csr[g_rowptr[d] + p] = src[e];
}

// ---------------------------------------------------------------------------
// Aggregation: warp per node, 32 lanes x float2 = 64-dim row.
// Neighbor indices loaded coalesced, broadcast via shfl. Mean normalized
// in-register; no atomics, agg written exactly once per node.
// ---------------------------------------------------------------------------
__global__ void agg_kernel(const float* __restrict__ h,
                           float* __restrict__ agg, int n) {
    int gw = (blockIdx.x * blockDim.x + threadIdx.x) >> 5;
    if (gw >= n) return;
    int lane = threadIdx.x & 31;
    int s0 = g_rowptr[gw], s1 = g_rowptr[gw + 1];
    float ax = 0.f, ay = 0.f;
    for (int base = s0; base < s1; base += 32) {
        int idx = 0;
        if (base + lane < s1) idx = g_csr[base + lane];
        int m = min(32, s1 - base);
        for (int j = 0; j < m; j++) {
            int s = __shfl_sync(0xffffffffu, idx, j);
            float2 v = *reinterpret_cast<const float2*>(h + s * DIM + lane * 2);
            ax += v.x; ay += v.y;
        }
    }
    float inv = 1.f / fmaxf((float)(s1 - s0), 1.f);
    float2 r; r.x = ax * inv; r.y = ay * inv;
    *reinterpret_cast<float2*>(agg + gw * DIM + lane * 2) = r;
}

// ---------------------------------------------------------------------------
// Linear: out[n,:] = act( concat(h[n,:], agg[n,:]) @ W + b )
// (agg arrives pre-normalized). Register-tiled: 64 nodes x 64 cols per block,
// 256 threads, 4x4 accumulators per thread, 1:8 LDS:FMA issue ratio.
// ---------------------------------------------------------------------------
#define SROW_STRIDE 132
#define SMEM_FLOATS (8192 + 64 + 64 * SROW_STRIDE)

__global__ __launch_bounds__(256) void linear_kernel(
        const float* __restrict__ h,
        const float* __restrict__ agg,
        const float* __restrict__ W,
        const float* __restrict__ b,
        float* __restrict__ out,
        int n, int relu) {
    extern __shared__ float smem[];
    float* sW   = smem;                 // [128][64]
    float* sb   = smem + 8192;          // [64]
    float* srow = smem + 8192 + 64;     // [64][SROW_STRIDE]

    int tid = threadIdx.x;

    for (int i = tid; i < 2 * DIM * DIM; i += 256) sW[i] = W[i];
    if (tid < DIM) sb[tid] = b[tid];
    __syncthreads();

    int cg = tid & 15;
    int ng = tid >> 4;
    int c0 = cg << 2;

    int ntiles = (n + 63) >> 6;
    for (int tile = blockIdx.x; tile < ntiles; tile += gridDim.x) {
        int base = tile << 6;

        // stage srow: [64 nodes][128] = concat(h, agg)
#pragma unroll
        for (int it = 0; it < 8; it++) {
            int idx = it * 256 + tid;
            int row = idx >> 5;
            int q   = idx & 31;
            int node = base + row;
            if (node < n) {
                float4 v;
                if (q < 16)
                    v = *reinterpret_cast<const float4*>(h + node * DIM + (q << 2));
                else
                    v = *reinterpret_cast<const float4*>(agg + node * DIM + ((q - 16) << 2));
                *reinterpret_cast<float4*>(&srow[row * SROW_STRIDE + (q << 2)]) = v;
            }
        }
        __syncthreads();

        float4 bv = *reinterpret_cast<const float4*>(&sb[c0]);
        float acc[4][4];
#pragma unroll
        for (int i = 0; i < 4; i++) {
            acc[i][0] = bv.x; acc[i][1] = bv.y; acc[i][2] = bv.z; acc[i][3] = bv.w;
        }

        int nb = ng << 2;
#pragma unroll 4
        for (int k = 0; k < 2 * DIM; k += 4) {
            float4 hv[4];
#pragma unroll
            for (int i = 0; i < 4; i++)
                hv[i] = *reinterpret_cast<const float4*>(&srow[(nb + i) * SROW_STRIDE + k]);
            float4 wv[4];
#pragma unroll
            for (int kk = 0; kk < 4; kk++)
                wv[kk] = *reinterpret_cast<const float4*>(&sW[(k + kk) * DIM + c0]);
#pragma unroll
            for (int i = 0; i < 4; i++) {
                acc[i][0] = fmaf(hv[i].x, wv[0].x, acc[i][0]);
                acc[i][1] = fmaf(hv[i].x, wv[0].y, acc[i][1]);
                acc[i][2] = fmaf(hv[i].x, wv[0].z, acc[i][2]);
                acc[i][3] = fmaf(hv[i].x, wv[0].w, acc[i][3]);
                acc[i][0] = fmaf(hv[i].y, wv[1].x, acc[i][0]);
                acc[i][1] = fmaf(hv[i].y, wv[1].y, acc[i][1]);
                acc[i][2] = fmaf(hv[i].y, wv[1].z, acc[i][2]);
                acc[i][3] = fmaf(hv[i].y, wv[1].w, acc[i][3]);
                acc[i][0] = fmaf(hv[i].z, wv[2].x, acc[i][0]);
                acc[i][1] = fmaf(hv[i].z, wv[2].y, acc[i][1]);
                acc[i][2] = fmaf(hv[i].z, wv[2].z, acc[i][2]);
                acc[i][3] = fmaf(hv[i].z, wv[2].w, acc[i][3]);
                acc[i][0] = fmaf(hv[i].w, wv[3].x, acc[i][0]);
                acc[i][1] = fmaf(hv[i].w, wv[3].y, acc[i][1]);
                acc[i][2] = fmaf(hv[i].w, wv[3].z, acc[i][2]);
                acc[i][3] = fmaf(hv[i].w, wv[3].w, acc[i][3]);
            }
        }

#pragma unroll
        for (int i = 0; i < 4; i++) {
            int node = base + nb + i;
            if (node < n) {
                float4 r = make_float4(acc[i][0], acc[i][1], acc[i][2], acc[i][3]);
                if (relu) {
                    r.x = fmaxf(r.x, 0.f); r.y = fmaxf(r.y, 0.f);
                    r.z = fmaxf(r.z, 0.f); r.w = fmaxf(r.w, 0.f);
                }
                *reinterpret_cast<float4*>(out + node * DIM + c0) = r;
            }
        }
        __syncthreads();
    }
}

// ---------------------------------------------------------------------------
// Launch
// Inputs: x[100000*64] f32, edge_index[2*2000000] i32,
//         W0[128*64] f32, b0[64] f32, W1[128*64] f32, b1[64] f32
// Output: [100000*64] f32
// ---------------------------------------------------------------------------
extern "C" void kernel_launch(void* const* d_in, const int* in_sizes, int n_in,
                              void* d_out, int out_size) {
    const float* x  = (const float*)d_in[0];
    const int*   ei = (const int*)  d_in[1];
    const float* W0 = (const float*)d_in[2];
    const float* b0 = (const float*)d_in[3];
    const float* W1 = (const float*)d_in[4];
    const float* b1 = (const float*)d_in[5];
    float* out = (float*)d_out;

    int n = in_sizes[0] / DIM;          // 100000
    int E = in_sizes[1] / 2;            // 2000000
    const int* src = ei;
    const int* dst = ei + E;

    float* agg;  cudaGetSymbolAddress((void**)&agg, g_agg);
    float* h1;   cudaGetSymbolAddress((void**)&h1,  g_h1);

    static int smem_set = 0;
    size_t smem_bytes = SMEM_FLOATS * sizeof(float);
    if (!smem_set) {
        cudaFuncSetAttribute(linear_kernel,
                             cudaFuncAttributeMaxDynamicSharedMemorySize,
                             (int)smem_bytes);
        smem_set = 1;
    }

    int nb = (n + 1023) / 1024;               // 98 scan blocks

    // ---- CSR build (once; reused by both layers) ----
    zero_cnt_kernel<<<(n + 255) / 256, 256>>>(n);
    deg_count_kernel<<<(E + 255) / 256, 256>>>(dst, E);
    scanA_kernel<<<nb, 1024>>>(n);
    scanB_kernel<<<1, 32>>>(nb, n, E);
    scanC_kernel<<<nb, 1024>>>(n);
    fill_kernel<<<(E + 255) / 256, 256>>>(src, dst, E);

    int agg_blocks = (int)(((long long)n * 32 + 255) / 256);

    // ---- layer 0 ----
    agg_kernel<<<agg_blocks, 256>>>(x, agg, n);
    linear_kernel<<<444, 256, smem_bytes>>>(x, agg, W0, b0, h1, n, /*relu=*/1);

    // ---- layer 1 ----
    agg_kernel<<<agg_blocks, 256>>>(h1, agg, n);
    linear_kernel<<<444, 256, smem_bytes>>>(h1, agg, W1, b1, out, n, /*relu=*/0);
}